// round 7
// baseline (speedup 1.0000x reference)
#include <cuda_runtime.h>
#include <cstdint>

#define BB 2
#define CC 512
#define LL 2304
#define NH 8
#define HD 64
#define KT 64
#define NT (LL/KT)        // 36
#define MW 72             // mask words per row (2304/32)

// ---------------- scratch (__device__ globals; no allocs allowed) ----------
__device__ float    g_q[(size_t)BB*NH*LL*HD];
__device__ float    g_k[(size_t)BB*NH*LL*HD];
__device__ float    g_v[(size_t)BB*NH*LL*HD];
__device__ float    g_att[(size_t)BB*CC*LL];
__device__ float    g_y[(size_t)BB*CC*LL];
__device__ float    g_xp[(size_t)BB*CC*LL];
__device__ unsigned g_mbits[(size_t)NH*LL*MW];

// ---------------- helpers ---------------------------------------------------
__device__ __forceinline__ uint32_t smem_u32(const void* p) {
    uint32_t a;
    asm("{ .reg .u64 t; cvta.to.shared.u64 t, %1; cvt.u32.u64 %0, t; }" : "=r"(a) : "l"(p));
    return a;
}
__device__ __forceinline__ uint32_t tf32b(float x) {
    uint32_t u; asm("cvt.rna.tf32.f32 %0, %1;" : "=r"(u) : "f"(x));
    return u;
}
__device__ __forceinline__ void mma8(float* c, const uint32_t* a, uint32_t b0, uint32_t b1) {
    asm volatile("mma.sync.aligned.m16n8k8.row.col.f32.tf32.tf32.f32 "
        "{%0,%1,%2,%3}, {%4,%5,%6,%7}, {%8,%9}, {%0,%1,%2,%3};"
        : "+f"(c[0]), "+f"(c[1]), "+f"(c[2]), "+f"(c[3])
        : "r"(a[0]), "r"(a[1]), "r"(a[2]), "r"(a[3]), "r"(b0), "r"(b1));
}
#define CP_ASYNC(dst, src) asm volatile("cp.async.cg.shared.global [%0], [%1], 16;" :: "r"(dst), "l"(src))
#define CP_COMMIT()        asm volatile("cp.async.commit_group;" ::: "memory")
#define CP_WAIT0()         asm volatile("cp.async.wait_group 0;" ::: "memory")

// ======================= attention kernel (unchanged) =======================
#define OFF_Q   0                 // 256 x 68
#define OFF_K   17408             // 2 x 64 x 68
#define OFF_V   26112             // 2 x 64 x 68
#define OFF_P   34816             // 8 warps x 32 x 68
#define OFF_REL 52224             // 68
#define SM_FLOATS 52292
#define SM_BYTES (SM_FLOATS*4)

__global__ __launch_bounds__(256) void pack_kernel(const int* __restrict__ mask)
{
    size_t idx = (size_t)blockIdx.x * 256 + threadIdx.x;   // word index
    const int4* src = (const int4*)(mask + idx * 32);
    unsigned bits = 0;
    #pragma unroll
    for (int i = 0; i < 8; i++) {
        int4 v = src[i];
        bits |= (v.x ? 1u : 0u) << (i*4 + 0);
        bits |= (v.y ? 1u : 0u) << (i*4 + 1);
        bits |= (v.z ? 1u : 0u) << (i*4 + 2);
        bits |= (v.w ? 1u : 0u) << (i*4 + 3);
    }
    g_mbits[idx] = bits;
}

__global__ __launch_bounds__(256) void attn_kernel(const float* __restrict__ rel)
{
    extern __shared__ float sm[];
    const int tid = threadIdx.x, wid = tid >> 5, lane = tid & 31;
    const int lr = lane >> 2, lc = lane & 3;
    const int b = blockIdx.z, h = blockIdx.y;
    const int q0 = blockIdx.x * 256;
    const int wq = wid * 32;
    const size_t bh = (size_t)(b * NH + h) * LL;

    float* Qs = sm + OFF_Q;
    float* Pw = sm + OFF_P + wid * (32 * 68);
    float* srel = sm + OFF_REL;

    if (tid < 65) srel[tid] = rel[h * 65 + tid];

    {
        const float4* qp = (const float4*)(g_q + (bh + q0) * HD);
        #pragma unroll
        for (int i = 0; i < 16; i++) {
            int fidx = i * 256 + tid;
            int row = fidx >> 4, c4 = (fidx & 15) * 4;
            float4 v = qp[fidx];
            float* d = Qs + row * 68 + c4;
            d[0] = v.x; d[1] = v.y; d[2] = v.z; d[3] = v.w;
        }
    }

    {
        const float* gk = g_k + bh * HD;
        const float* gv = g_v + bh * HD;
        uint32_t sk = smem_u32(sm + OFF_K), sv = smem_u32(sm + OFF_V);
        #pragma unroll
        for (int i = 0; i < 4; i++) {
            int fidx = i * 256 + tid;
            int row = fidx >> 4, c4 = (fidx & 15) * 4;
            uint32_t off = (uint32_t)(row * 68 + c4) * 4;
            CP_ASYNC(sk + off, gk + row * HD + c4);
            CP_ASYNC(sv + off, gv + row * HD + c4);
        }
        CP_COMMIT();
    }

    float oacc[2][8][4] = {};
    float lsum4[4] = {};
    const float rel0c = rel[h * 65 + 0], rel64c = rel[h * 65 + 64];

    for (int t = 0; t < NT; t++) {
        const int kt = t * KT;
        const int buf = t & 1;
        float* Ks = sm + OFF_K + buf * (64 * 68);
        float* Vs = sm + OFF_V + buf * (64 * 68);

        CP_WAIT0();
        __syncthreads();

        if (t + 1 < NT) {
            const float* gk = g_k + (bh + kt + KT) * HD;
            const float* gv = g_v + (bh + kt + KT) * HD;
            uint32_t sk = smem_u32(sm + OFF_K + (buf ^ 1) * (64 * 68));
            uint32_t sv = smem_u32(sm + OFF_V + (buf ^ 1) * (64 * 68));
            #pragma unroll
            for (int i = 0; i < 4; i++) {
                int fidx = i * 256 + tid;
                int row = fidx >> 4, c4 = (fidx & 15) * 4;
                uint32_t off = (uint32_t)(row * 68 + c4) * 4;
                CP_ASYNC(sk + off, gk + row * HD + c4);
                CP_ASYNC(sv + off, gv + row * HD + c4);
            }
            CP_COMMIT();
        }

        uint2 mwv[4];
        #pragma unroll
        for (int rr = 0; rr < 4; rr++) {
            int l = q0 + wq + (rr >> 1) * 16 + (rr & 1) * 8 + lr;
            mwv[rr] = *(const uint2*)(g_mbits + ((size_t)h * LL + l) * MW + 2 * t);
        }

        float sacc[2][8][4] = {};
        #pragma unroll
        for (int ks = 0; ks < 8; ks++) {
            uint32_t af[2][4];
            #pragma unroll
            for (int mt = 0; mt < 2; mt++) {
                const float* qb = Qs + (wq + mt * 16 + lr) * 68 + ks * 8 + lc;
                af[mt][0] = tf32b(qb[0]);
                af[mt][1] = tf32b(qb[8 * 68]);
                af[mt][2] = tf32b(qb[4]);
                af[mt][3] = tf32b(qb[8 * 68 + 4]);
            }
            #pragma unroll
            for (int j = 0; j < 8; j++) {
                const float* kb = Ks + (8 * j + lr) * 68 + ks * 8 + lc;
                uint32_t b0 = tf32b(kb[0]);
                uint32_t b1 = tf32b(kb[4]);
                mma8(sacc[0][j], af[0], b0, b1);
                mma8(sacc[1][j], af[1], b0, b1);
            }
        }

        #pragma unroll
        for (int mt = 0; mt < 2; mt++) {
            #pragma unroll
            for (int rh = 0; rh < 2; rh++) {
                const int rowloc = mt * 16 + rh * 8 + lr;
                const int l = q0 + wq + rowloc;
                const uint2 mw = mwv[mt * 2 + rh];
                const bool hi = (l - kt) >= 96;
                const bool lo = (kt - l) >= 33;
                float rsum = 0.f;
                #pragma unroll
                for (int j = 0; j < 8; j++) {
                    const int k0 = 8 * j + 2 * lc;
                    float v0 = sacc[mt][j][rh * 2 + 0];
                    float v1 = sacc[mt][j][rh * 2 + 1];
                    float b0v, b1v;
                    if (hi)      { b0v = rel64c; b1v = rel64c; }
                    else if (lo) { b0v = rel0c;  b1v = rel0c;  }
                    else {
                        int e = l - kt - k0 + 32;
                        int e0 = e < 0 ? 0 : (e > 64 ? 64 : e);
                        int e1 = e - 1; e1 = e1 < 0 ? 0 : (e1 > 64 ? 64 : e1);
                        b0v = srel[e0]; b1v = srel[e1];
                    }
                    unsigned mword = (j < 4) ? mw.x : mw.y;
                    float p0 = ((mword >> (k0 & 31)) & 1u)       ? __expf(fmaf(v0, 0.125f, b0v)) : 0.f;
                    float p1 = ((mword >> ((k0 + 1) & 31)) & 1u) ? __expf(fmaf(v1, 0.125f, b1v)) : 0.f;
                    rsum += p0 + p1;
                    uint2 pp; pp.x = tf32b(p0); pp.y = tf32b(p1);
                    *(uint2*)(Pw + rowloc * 68 + k0) = pp;
                }
                rsum += __shfl_xor_sync(0xffffffffu, rsum, 1);
                rsum += __shfl_xor_sync(0xffffffffu, rsum, 2);
                lsum4[mt * 2 + rh] += rsum;
            }
        }
        __syncwarp();

        #pragma unroll
        for (int ks = 0; ks < 8; ks++) {
            uint32_t af[2][4];
            #pragma unroll
            for (int mt = 0; mt < 2; mt++) {
                const uint32_t* pb = (const uint32_t*)(Pw + (mt * 16 + lr) * 68 + ks * 8 + lc);
                af[mt][0] = pb[0];
                af[mt][1] = pb[8 * 68];
                af[mt][2] = pb[4];
                af[mt][3] = pb[8 * 68 + 4];
            }
            #pragma unroll
            for (int j = 0; j < 8; j++) {
                const float* vb = Vs + (ks * 8 + lc) * 68 + 8 * j + lr;
                uint32_t b0 = tf32b(vb[0]);
                uint32_t b1 = tf32b(vb[4 * 68]);
                mma8(oacc[0][j], af[0], b0, b1);
                mma8(oacc[1][j], af[1], b0, b1);
            }
        }
        __syncwarp();
    }

    #pragma unroll
    for (int mt = 0; mt < 2; mt++) {
        #pragma unroll
        for (int rh = 0; rh < 2; rh++) {
            const int rowloc = mt * 16 + rh * 8 + lr;
            const float inv = 1.f / lsum4[mt * 2 + rh];
            #pragma unroll
            for (int j = 0; j < 8; j++) {
                float2 o;
                o.x = oacc[mt][j][rh * 2 + 0] * inv;
                o.y = oacc[mt][j][rh * 2 + 1] * inv;
                *(float2*)(Pw + rowloc * 68 + 8 * j + 2 * lc) = o;
            }
        }
    }
    __syncwarp();
    {
        const int l = q0 + wq + lane;
        float* ob = g_att + ((size_t)b * CC + h * 64) * LL + l;
        #pragma unroll
        for (int dd = 0; dd < 64; dd++)
            ob[(size_t)dd * LL] = Pw[lane * 68 + dd];
    }
}

// ======================= tf32 mma GEMMs, cp.async pipelined =================
#define XS_STRIDE 264
#define WS_STRIDE 68
#define PX_STAGE  16896               // 64 x 264 floats
#define PW_STAGE  4352                // 64 x 68 floats
#define P_X0 0
#define P_X1 PX_STAGE
#define P_W0 (2*PX_STAGE)
#define P_W1 (P_W0 + PW_STAGE)
#define P_TOTF (P_W0 + 2*PW_STAGE)    // 42496 floats
#define P_BYTES (P_TOTF*4)            // 169984 bytes

// xp = x + pos (pos broadcast over batch)
__global__ __launch_bounds__(256) void add_pos_kernel(
    const float* __restrict__ x, const float* __restrict__ pos)
{
    size_t i = (size_t)blockIdx.x * 256 + threadIdx.x;       // float4 index
    const size_t n4 = (size_t)CC * LL / 4;
    float4 xv = ((const float4*)x)[i];
    float4 pv = ((const float4*)pos)[i % n4];
    ((float4*)g_xp)[i] = make_float4(xv.x + pv.x, xv.y + pv.y, xv.z + pv.z, xv.w + pv.w);
}

// prefetch one k-chunk (X: 64 c-rows x 256 l, W raw: 64 oc x 64 c)
__device__ __forceinline__ void gemm_prefetch(
    float* sm, int stg, int tid, const float* __restrict__ src, int l0,
    const float* __restrict__ W, int oc0, int kt)
{
    uint32_t xs = smem_u32(sm + (stg ? P_X1 : P_X0));
    uint32_t ws = smem_u32(sm + (stg ? P_W1 : P_W0));
    #pragma unroll
    for (int i = 0; i < 16; i++) {
        int fidx = i * 256 + tid;
        int c = fidx >> 6, l4 = (fidx & 63) * 4;
        CP_ASYNC(xs + (uint32_t)(c * XS_STRIDE + l4) * 4, src + (size_t)(kt + c) * LL + l0 + l4);
    }
    #pragma unroll
    for (int i = 0; i < 4; i++) {
        int fidx = i * 256 + tid;
        int oc = fidx >> 4, c4 = (fidx & 15) * 4;
        CP_ASYNC(ws + (uint32_t)(oc * WS_STRIDE + c4) * 4, W + (size_t)(oc0 + oc) * CC + kt + c4);
    }
    CP_COMMIT();
}

// one k-chunk of 3-term-split tf32 mma (A from X smem, B raw W split at use)
__device__ __forceinline__ void gemm_chunk(
    const float* __restrict__ sm, int buf, int wid, int lr, int lc,
    float acc[2][8][4])
{
    const float* Xs = sm + (buf ? P_X1 : P_X0);
    const float* Wr = sm + (buf ? P_W1 : P_W0);
    #pragma unroll
    for (int ks = 0; ks < 8; ks++) {
        uint32_t ahi[2][4], alo[2][4];
        #pragma unroll
        for (int mt = 0; mt < 2; mt++) {
            const float* ab = Xs + (ks * 8 + lc) * XS_STRIDE + wid * 32 + mt * 16 + lr;
            float a0 = ab[0], a1 = ab[8], a2 = ab[4 * XS_STRIDE], a3 = ab[4 * XS_STRIDE + 8];
            ahi[mt][0] = tf32b(a0); alo[mt][0] = tf32b(a0 - __uint_as_float(ahi[mt][0]));
            ahi[mt][1] = tf32b(a1); alo[mt][1] = tf32b(a1 - __uint_as_float(ahi[mt][1]));
            ahi[mt][2] = tf32b(a2); alo[mt][2] = tf32b(a2 - __uint_as_float(ahi[mt][2]));
            ahi[mt][3] = tf32b(a3); alo[mt][3] = tf32b(a3 - __uint_as_float(ahi[mt][3]));
        }
        #pragma unroll
        for (int j = 0; j < 8; j++) {
            const float* wr = Wr + (8 * j + lr) * WS_STRIDE + ks * 8 + lc;
            float w0 = wr[0], w1 = wr[4];
            uint32_t bh0 = tf32b(w0), bh1 = tf32b(w1);
            uint32_t bl0 = tf32b(w0 - __uint_as_float(bh0));
            uint32_t bl1 = tf32b(w1 - __uint_as_float(bh1));
            mma8(acc[0][j], ahi[0], bh0, bh1);
            mma8(acc[1][j], ahi[1], bh0, bh1);
            mma8(acc[0][j], alo[0], bh0, bh1);
            mma8(acc[1][j], alo[1], bh0, bh1);
            mma8(acc[0][j], ahi[0], bl0, bl1);
            mma8(acc[1][j], ahi[1], bl0, bl1);
        }
    }
}

// out[b,h,l,d] = sum_c xp[b,c,l] * W[h*64+d, c] + bias
__global__ __launch_bounds__(256) void gemm_qkv_mma(
    const float* __restrict__ Wq, const float* __restrict__ bq,
    const float* __restrict__ Wk, const float* __restrict__ bk,
    const float* __restrict__ Wv, const float* __restrict__ bv)
{
    extern __shared__ float sm[];
    const int tid = threadIdx.x, wid = tid >> 5, lane = tid & 31;
    const int lr = lane >> 2, lc = lane & 3;
    const int l0 = blockIdx.x * 256;
    const int h = blockIdx.y;
    const int zz = blockIdx.z;
    const int b = zz / 3, proj = zz % 3;
    const float* W    = (proj == 0) ? Wq : (proj == 1) ? Wk : Wv;
    const float* bias = (proj == 0) ? bq : (proj == 1) ? bk : bv;
    float* out        = (proj == 0) ? g_q : (proj == 1) ? g_k : g_v;
    const int oc0 = h * 64;
    const float* src = g_xp + (size_t)b * CC * LL;

    float acc[2][8][4] = {};

    gemm_prefetch(sm, 0, tid, src, l0, W, oc0, 0);
    #pragma unroll 1
    for (int ci = 0; ci < CC / 64; ci++) {
        const int buf = ci & 1;
        CP_WAIT0();
        __syncthreads();
        if (ci + 1 < CC / 64)
            gemm_prefetch(sm, buf ^ 1, tid, src, l0, W, oc0, (ci + 1) * 64);
        gemm_chunk(sm, buf, wid, lr, lc, acc);
    }

    #pragma unroll
    for (int j = 0; j < 8; j++) {
        float2 bv2 = *(const float2*)(bias + oc0 + 8 * j + 2 * lc);
        #pragma unroll
        for (int mt = 0; mt < 2; mt++) {
            int l = l0 + wid * 32 + mt * 16 + lr;
            size_t rb = ((size_t)(b * NH + h) * LL + l) * HD + 8 * j + 2 * lc;
            float2 r0 = make_float2(acc[mt][j][0] + bv2.x, acc[mt][j][1] + bv2.y);
            float2 r1 = make_float2(acc[mt][j][2] + bv2.x, acc[mt][j][3] + bv2.y);
            *(float2*)(out + rb) = r0;
            *(float2*)(out + rb + (size_t)8 * HD) = r1;
        }
    }
}

// y[b,oc,l] = sum_c Wo[oc,c]*att[b,c,l] + bo[oc] + x[b,oc,l]
__global__ __launch_bounds__(256) void gemm_proj_mma(
    const float* __restrict__ W, const float* __restrict__ bias,
    const float* __restrict__ xres)
{
    extern __shared__ float sm[];
    const int tid = threadIdx.x, wid = tid >> 5, lane = tid & 31;
    const int lr = lane >> 2, lc = lane & 3;
    const int l0 = blockIdx.x * 256;
    const int oc0 = blockIdx.y * 64;
    const int b = blockIdx.z;
    const float* src = g_att + (size_t)b * CC * LL;

    float acc[2][8][4] = {};

    gemm_prefetch(sm, 0, tid, src, l0, W, oc0, 0);
    #pragma unroll 1
    for (int ci = 0; ci < CC / 64; ci++) {
        const int buf = ci & 1;
        CP_WAIT0();
        __syncthreads();
        if (ci + 1 < CC / 64)
            gemm_prefetch(sm, buf ^ 1, tid, src, l0, W, oc0, (ci + 1) * 64);
        gemm_chunk(sm, buf, wid, lr, lc, acc);
    }

    // transpose via per-warp smem, then coalesced (oc, l) store + bias + residual
    __syncthreads();
    float* Pw = sm + wid * (32 * 66);
    #pragma unroll
    for (int j = 0; j < 8; j++) {
        #pragma unroll
        for (int mt = 0; mt < 2; mt++) {
            int r0 = mt * 16 + lr;
            *(float2*)(Pw + r0 * 66 + 8 * j + 2 * lc) = make_float2(acc[mt][j][0], acc[mt][j][1]);
            *(float2*)(Pw + (r0 + 8) * 66 + 8 * j + 2 * lc) = make_float2(acc[mt][j][2], acc[mt][j][3]);
        }
    }
    __syncwarp();
    {
        const int l = l0 + wid * 32 + lane;
        #pragma unroll 8
        for (int dd = 0; dd < 64; dd++) {
            int oc = oc0 + dd;
            size_t gidx = ((size_t)(b * CC + oc)) * LL + l;
            g_y[gidx] = Pw[lane * 66 + dd] + bias[oc] + xres[gidx];
        }
    }
}

// ---------------------------------------------------------------------------
// LayerNorm: 32 pixels x 512 channels per CTA, coalesced over l.
// ---------------------------------------------------------------------------
__global__ __launch_bounds__(256) void ln_kernel(
    const float* __restrict__ gamma, const float* __restrict__ beta,
    float* __restrict__ out)
{
    const int w = threadIdx.x >> 5, lane = threadIdx.x & 31;
    const int p0 = blockIdx.x * 32;
    const int b = p0 / LL;
    const int l = p0 % LL + lane;
    const float* yb = g_y + (size_t)b * CC * LL;

    float vals[64];
    float s = 0.f, s2 = 0.f;
    #pragma unroll
    for (int i = 0; i < 64; i++) {
        float v = yb[(size_t)(w * 64 + i) * LL + l];
        vals[i] = v; s += v; s2 += v * v;
    }
    __shared__ float ss[8][32], ss2[8][32];
    ss[w][lane] = s; ss2[w][lane] = s2;
    __syncthreads();
    float st = 0.f, st2 = 0.f;
    #pragma unroll
    for (int i = 0; i < 8; i++) { st += ss[i][lane]; st2 += ss2[i][lane]; }
    float mean = st * (1.f / CC);
    float var = st2 * (1.f / CC) - mean * mean;
    float rs = rsqrtf(var + 1e-5f);

    float* ob = out + (size_t)b * CC * LL;
    #pragma unroll
    for (int i = 0; i < 64; i++) {
        int c = w * 64 + i;
        ob[(size_t)c * LL + l] = (vals[i] - mean) * rs * gamma[c] + beta[c];
    }
}

// ---------------------------------------------------------------------------
extern "C" void kernel_launch(void* const* d_in, const int* in_sizes, int n_in,
                              void* d_out, int out_size)
{
    const float* x    = (const float*)d_in[0];
    const int*   mask = (const int*)d_in[1];
    const float* pos  = (const float*)d_in[2];
    const float* Wq = (const float*)d_in[3];
    const float* bq = (const float*)d_in[4];
    const float* Wk = (const float*)d_in[5];
    const float* bk = (const float*)d_in[6];
    const float* Wv = (const float*)d_in[7];
    const float* bv = (const float*)d_in[8];
    const float* Wo = (const float*)d_in[9];
    const float* bo = (const float*)d_in[10];
    const float* rel = (const float*)d_in[11];
    const float* gam = (const float*)d_in[12];
    const float* bet = (const float*)d_in[13];
    float* out = (float*)d_out;

    static bool attr_set = false;
    if (!attr_set) {
        cudaFuncSetAttribute(attn_kernel, cudaFuncAttributeMaxDynamicSharedMemorySize, SM_BYTES);
        cudaFuncSetAttribute(gemm_qkv_mma, cudaFuncAttributeMaxDynamicSharedMemorySize, P_BYTES);
        cudaFuncSetAttribute(gemm_proj_mma, cudaFuncAttributeMaxDynamicSharedMemorySize, P_BYTES);
        attr_set = true;
    }

    add_pos_kernel<<<(BB * CC * LL) / 4 / 256, 256>>>(x, pos);
    gemm_qkv_mma<<<dim3(LL / 256, NH, BB * 3), 256, P_BYTES>>>(Wq, bq, Wk, bk, Wv, bv);
    pack_kernel<<<(NH * LL * MW) / 256, 256>>>(mask);
    attn_kernel<<<dim3(LL / 256, NH, BB), 256, SM_BYTES>>>(rel);
    gemm_proj_mma<<<dim3(LL / 256, CC / 64, BB), 256, P_BYTES>>>(Wo, bo, x);
    ln_kernel<<<(BB * LL) / 32, 256>>>(gam, bet, out);
}

// round 9
// speedup vs baseline: 1.0161x; 1.0161x over previous
#include <cuda_runtime.h>
#include <cstdint>

#define BB 2
#define CC 512
#define LL 2304
#define NH 8
#define HD 64
#define KT 64
#define NT (LL/KT)        // 36
#define MW 72             // mask words per row (2304/32)

// ---------------- scratch (__device__ globals; no allocs allowed) ----------
__device__ float    g_q[(size_t)BB*NH*LL*HD];   // tf32-rounded
__device__ float    g_k[(size_t)BB*NH*LL*HD];   // tf32-rounded
__device__ float    g_v[(size_t)BB*NH*LL*HD];   // tf32-rounded
__device__ float    g_att[(size_t)BB*CC*LL];
__device__ float    g_y[(size_t)BB*CC*LL];
__device__ float    g_xp[(size_t)BB*CC*LL];
__device__ unsigned g_mbits[(size_t)NH*LL*MW];

// ---------------- helpers ---------------------------------------------------
__device__ __forceinline__ uint32_t smem_u32(const void* p) {
    uint32_t a;
    asm("{ .reg .u64 t; cvta.to.shared.u64 t, %1; cvt.u32.u64 %0, t; }" : "=r"(a) : "l"(p));
    return a;
}
__device__ __forceinline__ uint32_t tf32b(float x) {
    uint32_t u; asm("cvt.rna.tf32.f32 %0, %1;" : "=r"(u) : "f"(x));
    return u;
}
__device__ __forceinline__ float rna(float x) { return __uint_as_float(tf32b(x)); }
__device__ __forceinline__ void mma8(float* c, const uint32_t* a, uint32_t b0, uint32_t b1) {
    asm volatile("mma.sync.aligned.m16n8k8.row.col.f32.tf32.tf32.f32 "
        "{%0,%1,%2,%3}, {%4,%5,%6,%7}, {%8,%9}, {%0,%1,%2,%3};"
        : "+f"(c[0]), "+f"(c[1]), "+f"(c[2]), "+f"(c[3])
        : "r"(a[0]), "r"(a[1]), "r"(a[2]), "r"(a[3]), "r"(b0), "r"(b1));
}
#define CP_ASYNC(dst, src) asm volatile("cp.async.cg.shared.global [%0], [%1], 16;" :: "r"(dst), "l"(src))
#define CP_COMMIT()        asm volatile("cp.async.commit_group;" ::: "memory")
#define CP_WAIT0()         asm volatile("cp.async.wait_group 0;" ::: "memory")

// ======================= attention kernel ===================================
#define OFF_Q   0                 // 256 x 68
#define OFF_K   17408             // 2 x 64 x 68
#define OFF_V   26112             // 2 x 64 x 68
#define OFF_P   34816             // 8 warps x 32 x 68
#define OFF_REL 52224             // 68
#define SM_FLOATS 52292
#define SM_BYTES (SM_FLOATS*4)

__global__ __launch_bounds__(256) void pack_kernel(const int* __restrict__ mask)
{
    size_t idx = (size_t)blockIdx.x * 256 + threadIdx.x;   // word index
    const int4* src = (const int4*)(mask + idx * 32);
    unsigned bits = 0;
    #pragma unroll
    for (int i = 0; i < 8; i++) {
        int4 v = src[i];
        bits |= (v.x ? 1u : 0u) << (i*4 + 0);
        bits |= (v.y ? 1u : 0u) << (i*4 + 1);
        bits |= (v.z ? 1u : 0u) << (i*4 + 2);
        bits |= (v.w ? 1u : 0u) << (i*4 + 3);
    }
    g_mbits[idx] = bits;
}

__global__ __launch_bounds__(256) void attn_kernel(const float* __restrict__ rel)
{
    extern __shared__ float sm[];
    const int tid = threadIdx.x, wid = tid >> 5, lane = tid & 31;
    const int lr = lane >> 2, lc = lane & 3;
    const int b = blockIdx.z, h = blockIdx.y;
    const int q0 = blockIdx.x * 256;
    const int wq = wid * 32;
    const size_t bh = (size_t)(b * NH + h) * LL;

    float* Qs = sm + OFF_Q;
    float* Pw = sm + OFF_P + wid * (32 * 68);
    float* srel = sm + OFF_REL;

    if (tid < 65) srel[tid] = rel[h * 65 + tid];

    // Q (already tf32-rounded) -> SMEM
    {
        const float4* qp = (const float4*)(g_q + (bh + q0) * HD);
        #pragma unroll
        for (int i = 0; i < 16; i++) {
            int fidx = i * 256 + tid;
            int row = fidx >> 4, c4 = (fidx & 15) * 4;
            float4 v = qp[fidx];
            float* d = Qs + row * 68 + c4;
            d[0] = v.x; d[1] = v.y; d[2] = v.z; d[3] = v.w;
        }
    }

    {
        const float* gk = g_k + bh * HD;
        const float* gv = g_v + bh * HD;
        uint32_t sk = smem_u32(sm + OFF_K), sv = smem_u32(sm + OFF_V);
        #pragma unroll
        for (int i = 0; i < 4; i++) {
            int fidx = i * 256 + tid;
            int row = fidx >> 4, c4 = (fidx & 15) * 4;
            uint32_t off = (uint32_t)(row * 68 + c4) * 4;
            CP_ASYNC(sk + off, gk + row * HD + c4);
            CP_ASYNC(sv + off, gv + row * HD + c4);
        }
        CP_COMMIT();
    }

    float oacc[2][8][4] = {};
    float lsum4[4] = {};
    const float rel0c = rel[h * 65 + 0], rel64c = rel[h * 65 + 64];

    for (int t = 0; t < NT; t++) {
        const int kt = t * KT;
        const int buf = t & 1;
        const uint32_t* Ks = (const uint32_t*)(sm + OFF_K + buf * (64 * 68));
        const uint32_t* Vs = (const uint32_t*)(sm + OFF_V + buf * (64 * 68));

        CP_WAIT0();
        __syncthreads();

        if (t + 1 < NT) {
            const float* gk = g_k + (bh + kt + KT) * HD;
            const float* gv = g_v + (bh + kt + KT) * HD;
            uint32_t sk = smem_u32(sm + OFF_K + (buf ^ 1) * (64 * 68));
            uint32_t sv = smem_u32(sm + OFF_V + (buf ^ 1) * (64 * 68));
            #pragma unroll
            for (int i = 0; i < 4; i++) {
                int fidx = i * 256 + tid;
                int row = fidx >> 4, c4 = (fidx & 15) * 4;
                uint32_t off = (uint32_t)(row * 68 + c4) * 4;
                CP_ASYNC(sk + off, gk + row * HD + c4);
                CP_ASYNC(sv + off, gv + row * HD + c4);
            }
            CP_COMMIT();
        }

        uint2 mwv[4];
        #pragma unroll
        for (int rr = 0; rr < 4; rr++) {
            int l = q0 + wq + (rr >> 1) * 16 + (rr & 1) * 8 + lr;
            mwv[rr] = *(const uint2*)(g_mbits + ((size_t)h * LL + l) * MW + 2 * t);
        }

        // ---- QK: fragments loaded as raw tf32 bits (no cvt) ----
        float sacc[2][8][4] = {};
        const uint32_t* Qb = (const uint32_t*)Qs;
        #pragma unroll
        for (int ks = 0; ks < 8; ks++) {
            uint32_t af[2][4];
            #pragma unroll
            for (int mt = 0; mt < 2; mt++) {
                const uint32_t* qb = Qb + (wq + mt * 16 + lr) * 68 + ks * 8 + lc;
                af[mt][0] = qb[0];
                af[mt][1] = qb[8 * 68];
                af[mt][2] = qb[4];
                af[mt][3] = qb[8 * 68 + 4];
            }
            #pragma unroll
            for (int j = 0; j < 8; j++) {
                const uint32_t* kb = Ks + (8 * j + lr) * 68 + ks * 8 + lc;
                uint32_t b0 = kb[0];
                uint32_t b1 = kb[4];
                mma8(sacc[0][j], af[0], b0, b1);
                mma8(sacc[1][j], af[1], b0, b1);
            }
        }

        // ---- softmax epilogue -> P (tf32 bits) in per-warp SMEM ----
        #pragma unroll
        for (int mt = 0; mt < 2; mt++) {
            #pragma unroll
            for (int rh = 0; rh < 2; rh++) {
                const int rowloc = mt * 16 + rh * 8 + lr;
                const int l = q0 + wq + rowloc;
                const uint2 mw = mwv[mt * 2 + rh];
                const bool hi = (l - kt) >= 96;
                const bool lo = (kt - l) >= 33;
                float rsum = 0.f;
                #pragma unroll
                for (int j = 0; j < 8; j++) {
                    const int k0 = 8 * j + 2 * lc;
                    float v0 = sacc[mt][j][rh * 2 + 0];
                    float v1 = sacc[mt][j][rh * 2 + 1];
                    float b0v, b1v;
                    if (hi)      { b0v = rel64c; b1v = rel64c; }
                    else if (lo) { b0v = rel0c;  b1v = rel0c;  }
                    else {
                        int e = l - kt - k0 + 32;
                        int e0 = e < 0 ? 0 : (e > 64 ? 64 : e);
                        int e1 = e - 1; e1 = e1 < 0 ? 0 : (e1 > 64 ? 64 : e1);
                        b0v = srel[e0]; b1v = srel[e1];
                    }
                    unsigned mword = (j < 4) ? mw.x : mw.y;
                    float p0 = ((mword >> (k0 & 31)) & 1u)       ? __expf(fmaf(v0, 0.125f, b0v)) : 0.f;
                    float p1 = ((mword >> ((k0 + 1) & 31)) & 1u) ? __expf(fmaf(v1, 0.125f, b1v)) : 0.f;
                    rsum += p0 + p1;
                    uint2 pp; pp.x = tf32b(p0); pp.y = tf32b(p1);
                    *(uint2*)(Pw + rowloc * 68 + k0) = pp;
                }
                rsum += __shfl_xor_sync(0xffffffffu, rsum, 1);
                rsum += __shfl_xor_sync(0xffffffffu, rsum, 2);
                lsum4[mt * 2 + rh] += rsum;
            }
        }
        __syncwarp();

        // ---- PV: P bits + V bits straight from SMEM (no cvt) ----
        #pragma unroll
        for (int ks = 0; ks < 8; ks++) {
            uint32_t af[2][4];
            #pragma unroll
            for (int mt = 0; mt < 2; mt++) {
                const uint32_t* pb = (const uint32_t*)(Pw + (mt * 16 + lr) * 68 + ks * 8 + lc);
                af[mt][0] = pb[0];
                af[mt][1] = pb[8 * 68];
                af[mt][2] = pb[4];
                af[mt][3] = pb[8 * 68 + 4];
            }
            #pragma unroll
            for (int j = 0; j < 8; j++) {
                const uint32_t* vb = Vs + (ks * 8 + lc) * 68 + 8 * j + lr;
                uint32_t b0 = vb[0];
                uint32_t b1 = vb[4 * 68];
                mma8(oacc[0][j], af[0], b0, b1);
                mma8(oacc[1][j], af[1], b0, b1);
            }
        }
        __syncwarp();
    }

    #pragma unroll
    for (int mt = 0; mt < 2; mt++) {
        #pragma unroll
        for (int rh = 0; rh < 2; rh++) {
            const int rowloc = mt * 16 + rh * 8 + lr;
            const float inv = 1.f / lsum4[mt * 2 + rh];
            #pragma unroll
            for (int j = 0; j < 8; j++) {
                float2 o;
                o.x = oacc[mt][j][rh * 2 + 0] * inv;
                o.y = oacc[mt][j][rh * 2 + 1] * inv;
                *(float2*)(Pw + rowloc * 68 + 8 * j + 2 * lc) = o;
            }
        }
    }
    __syncwarp();
    {
        const int l = q0 + wq + lane;
        float* ob = g_att + ((size_t)b * CC + h * 64) * LL + l;
        #pragma unroll
        for (int dd = 0; dd < 64; dd++)
            ob[(size_t)dd * LL] = Pw[lane * 68 + dd];
    }
}

// ======================= tf32 mma GEMMs, cp.async pipelined =================
#define XS_STRIDE 264
#define WS_STRIDE 68
#define PX_STAGE  16896               // 64 x 264 floats
#define PW_STAGE  4352                // 64 x 68 floats
#define P_X0 0
#define P_X1 PX_STAGE
#define P_W0 (2*PX_STAGE)
#define P_W1 (P_W0 + PW_STAGE)
#define P_TOTF (P_W0 + 2*PW_STAGE)    // 42496 floats
#define P_BYTES (P_TOTF*4)            // 169984 bytes

__global__ __launch_bounds__(256) void add_pos_kernel(
    const float* __restrict__ x, const float* __restrict__ pos)
{
    size_t i = (size_t)blockIdx.x * 256 + threadIdx.x;       // float4 index
    const size_t n4 = (size_t)CC * LL / 4;
    float4 xv = ((const float4*)x)[i];
    float4 pv = ((const float4*)pos)[i % n4];
    ((float4*)g_xp)[i] = make_float4(xv.x + pv.x, xv.y + pv.y, xv.z + pv.z, xv.w + pv.w);
}

__device__ __forceinline__ void gemm_prefetch(
    float* sm, int stg, int tid, const float* __restrict__ src, int l0,
    const float* __restrict__ W, int oc0, int kt)
{
    uint32_t xs = smem_u32(sm + (stg ? P_X1 : P_X0));
    uint32_t ws = smem_u32(sm + (stg ? P_W1 : P_W0));
    #pragma unroll
    for (int i = 0; i < 16; i++) {
        int fidx = i * 256 + tid;
        int c = fidx >> 6, l4 = (fidx & 63) * 4;
        CP_ASYNC(xs + (uint32_t)(c * XS_STRIDE + l4) * 4, src + (size_t)(kt + c) * LL + l0 + l4);
    }
    #pragma unroll
    for (int i = 0; i < 4; i++) {
        int fidx = i * 256 + tid;
        int oc = fidx >> 4, c4 = (fidx & 15) * 4;
        CP_ASYNC(ws + (uint32_t)(oc * WS_STRIDE + c4) * 4, W + (size_t)(oc0 + oc) * CC + kt + c4);
    }
    CP_COMMIT();
}

__device__ __forceinline__ void gemm_chunk(
    const float* __restrict__ sm, int buf, int wid, int lr, int lc,
    float acc[2][8][4])
{
    const float* Xs = sm + (buf ? P_X1 : P_X0);
    const float* Wr = sm + (buf ? P_W1 : P_W0);
    #pragma unroll
    for (int ks = 0; ks < 8; ks++) {
        uint32_t ahi[2][4], alo[2][4];
        #pragma unroll
        for (int mt = 0; mt < 2; mt++) {
            const float* ab = Xs + (ks * 8 + lc) * XS_STRIDE + wid * 32 + mt * 16 + lr;
            float a0 = ab[0], a1 = ab[8], a2 = ab[4 * XS_STRIDE], a3 = ab[4 * XS_STRIDE + 8];
            ahi[mt][0] = tf32b(a0); alo[mt][0] = tf32b(a0 - __uint_as_float(ahi[mt][0]));
            ahi[mt][1] = tf32b(a1); alo[mt][1] = tf32b(a1 - __uint_as_float(ahi[mt][1]));
            ahi[mt][2] = tf32b(a2); alo[mt][2] = tf32b(a2 - __uint_as_float(ahi[mt][2]));
            ahi[mt][3] = tf32b(a3); alo[mt][3] = tf32b(a3 - __uint_as_float(ahi[mt][3]));
        }
        #pragma unroll
        for (int j = 0; j < 8; j++) {
            const float* wr = Wr + (8 * j + lr) * WS_STRIDE + ks * 8 + lc;
            float w0 = wr[0], w1 = wr[4];
            uint32_t bh0 = tf32b(w0), bh1 = tf32b(w1);
            uint32_t bl0 = tf32b(w0 - __uint_as_float(bh0));
            uint32_t bl1 = tf32b(w1 - __uint_as_float(bh1));
            mma8(acc[0][j], ahi[0], bh0, bh1);
            mma8(acc[1][j], ahi[1], bh0, bh1);
            mma8(acc[0][j], alo[0], bh0, bh1);
            mma8(acc[1][j], alo[1], bh0, bh1);
            mma8(acc[0][j], ahi[0], bl0, bl1);
            mma8(acc[1][j], ahi[1], bl0, bl1);
        }
    }
}

// out[b,h,l,d] = tf32_round( sum_c xp[b,c,l] * W[h*64+d, c] + bias )
__global__ __launch_bounds__(256) void gemm_qkv_mma(
    const float* __restrict__ Wq, const float* __restrict__ bq,
    const float* __restrict__ Wk, const float* __restrict__ bk,
    const float* __restrict__ Wv, const float* __restrict__ bv)
{
    extern __shared__ float sm[];
    const int tid = threadIdx.x, wid = tid >> 5, lane = tid & 31;
    const int lr = lane >> 2, lc = lane & 3;
    const int l0 = blockIdx.x * 256;
    const int h = blockIdx.y;
    const int zz = blockIdx.z;
    const int b = zz / 3, proj = zz % 3;
    const float* W    = (proj == 0) ? Wq : (proj == 1) ? Wk : Wv;
    const float* bias = (proj == 0) ? bq : (proj == 1) ? bk : bv;
    float* out        = (proj == 0) ? g_q : (proj == 1) ? g_k : g_v;
    const int oc0 = h * 64;
    const float* src = g_xp + (size_t)b * CC * LL;

    float acc[2][8][4] = {};

    gemm_prefetch(sm, 0, tid, src, l0, W, oc0, 0);
    #pragma unroll 1
    for (int ci = 0; ci < CC / 64; ci++) {
        const int buf = ci & 1;
        CP_WAIT0();
        __syncthreads();
        if (ci + 1 < CC / 64)
            gemm_prefetch(sm, buf ^ 1, tid, src, l0, W, oc0, (ci + 1) * 64);
        gemm_chunk(sm, buf, wid, lr, lc, acc);
    }

    #pragma unroll
    for (int j = 0; j < 8; j++) {
        float2 bv2 = *(const float2*)(bias + oc0 + 8 * j + 2 * lc);
        #pragma unroll
        for (int mt = 0; mt < 2; mt++) {
            int l = l0 + wid * 32 + mt * 16 + lr;
            size_t rb = ((size_t)(b * NH + h) * LL + l) * HD + 8 * j + 2 * lc;
            float2 r0 = make_float2(rna(acc[mt][j][0] + bv2.x), rna(acc[mt][j][1] + bv2.y));
            float2 r1 = make_float2(rna(acc[mt][j][2] + bv2.x), rna(acc[mt][j][3] + bv2.y));
            *(float2*)(out + rb) = r0;
            *(float2*)(out + rb + (size_t)8 * HD) = r1;
        }
    }
}

// y[b,oc,l] = sum_c Wo[oc,c]*att[b,c,l] + bo[oc] + x[b,oc,l]
__global__ __launch_bounds__(256) void gemm_proj_mma(
    const float* __restrict__ W, const float* __restrict__ bias,
    const float* __restrict__ xres)
{
    extern __shared__ float sm[];
    const int tid = threadIdx.x, wid = tid >> 5, lane = tid & 31;
    const int lr = lane >> 2, lc = lane & 3;
    const int l0 = blockIdx.x * 256;
    const int oc0 = blockIdx.y * 64;
    const int b = blockIdx.z;
    const float* src = g_att + (size_t)b * CC * LL;

    float acc[2][8][4] = {};

    gemm_prefetch(sm, 0, tid, src, l0, W, oc0, 0);
    #pragma unroll 1
    for (int ci = 0; ci < CC / 64; ci++) {
        const int buf = ci & 1;
        CP_WAIT0();
        __syncthreads();
        if (ci + 1 < CC / 64)
            gemm_prefetch(sm, buf ^ 1, tid, src, l0, W, oc0, (ci + 1) * 64);
        gemm_chunk(sm, buf, wid, lr, lc, acc);
    }

    __syncthreads();
    float* Pw = sm + wid * (32 * 66);
    #pragma unroll
    for (int j = 0; j < 8; j++) {
        #pragma unroll
        for (int mt = 0; mt < 2; mt++) {
            int r0 = mt * 16 + lr;
            *(float2*)(Pw + r0 * 66 + 8 * j + 2 * lc) = make_float2(acc[mt][j][0], acc[mt][j][1]);
            *(float2*)(Pw + (r0 + 8) * 66 + 8 * j + 2 * lc) = make_float2(acc[mt][j][2], acc[mt][j][3]);
        }
    }
    __syncwarp();
    {
        const int l = l0 + wid * 32 + lane;
        #pragma unroll 8
        for (int dd = 0; dd < 64; dd++) {
            int oc = oc0 + dd;
            size_t gidx = ((size_t)(b * CC + oc)) * LL + l;
            g_y[gidx] = Pw[lane * 66 + dd] + bias[oc] + xres[gidx];
        }
    }
}

// ---------------------------------------------------------------------------
// LayerNorm: 32 pixels x 512 channels per CTA, coalesced over l.
// ---------------------------------------------------------------------------
__global__ __launch_bounds__(256) void ln_kernel(
    const float* __restrict__ gamma, const float* __restrict__ beta,
    float* __restrict__ out)
{
    const int w = threadIdx.x >> 5, lane = threadIdx.x & 31;
    const int p0 = blockIdx.x * 32;
    const int b = p0 / LL;
    const int l = p0 % LL + lane;
    const float* yb = g_y + (size_t)b * CC * LL;

    float vals[64];
    float s = 0.f, s2 = 0.f;
    #pragma unroll
    for (int i = 0; i < 64; i++) {
        float v = yb[(size_t)(w * 64 + i) * LL + l];
        vals[i] = v; s += v; s2 += v * v;
    }
    __shared__ float ss[8][32], ss2[8][32];
    ss[w][lane] = s; ss2[w][lane] = s2;
    __syncthreads();
    float st = 0.f, st2 = 0.f;
    #pragma unroll
    for (int i = 0; i < 8; i++) { st += ss[i][lane]; st2 += ss2[i][lane]; }
    float mean = st * (1.f / CC);
    float var = st2 * (1.f / CC) - mean * mean;
    float rs = rsqrtf(var + 1e-5f);

    float* ob = out + (size_t)b * CC * LL;
    #pragma unroll
    for (int i = 0; i < 64; i++) {
        int c = w * 64 + i;
        ob[(size_t)c * LL + l] = (vals[i] - mean) * rs * gamma[c] + beta[c];
    }
}

// ---------------------------------------------------------------------------
extern "C" void kernel_launch(void* const* d_in, const int* in_sizes, int n_in,
                              void* d_out, int out_size)
{
    const float* x    = (const float*)d_in[0];
    const int*   mask = (const int*)d_in[1];
    const float* pos  = (const float*)d_in[2];
    const float* Wq = (const float*)d_in[3];
    const float* bq = (const float*)d_in[4];
    const float* Wk = (const float*)d_in[5];
    const float* bk = (const float*)d_in[6];
    const float* Wv = (const float*)d_in[7];
    const float* bv = (const float*)d_in[8];
    const float* Wo = (const float*)d_in[9];
    const float* bo = (const float*)d_in[10];
    const float* rel = (const float*)d_in[11];
    const float* gam = (const float*)d_in[12];
    const float* bet = (const float*)d_in[13];
    float* out = (float*)d_out;

    static bool attr_set = false;
    if (!attr_set) {
        cudaFuncSetAttribute(attn_kernel, cudaFuncAttributeMaxDynamicSharedMemorySize, SM_BYTES);
        cudaFuncSetAttribute(gemm_qkv_mma, cudaFuncAttributeMaxDynamicSharedMemorySize, P_BYTES);
        cudaFuncSetAttribute(gemm_proj_mma, cudaFuncAttributeMaxDynamicSharedMemorySize, P_BYTES);
        attr_set = true;
    }

    add_pos_kernel<<<(BB * CC * LL) / 4 / 256, 256>>>(x, pos);
    gemm_qkv_mma<<<dim3(LL / 256, NH, BB * 3), 256, P_BYTES>>>(Wq, bq, Wk, bk, Wv, bv);
    pack_kernel<<<(NH * LL * MW) / 256, 256>>>(mask);
    attn_kernel<<<dim3(LL / 256, NH, BB), 256, SM_BYTES>>>(rel);
    gemm_proj_mma<<<dim3(LL / 256, CC / 64, BB), 256, P_BYTES>>>(Wo, bo, x);
    ln_kernel<<<(BB * LL) / 32, 256>>>(gam, bet, out);
}

// round 10
// speedup vs baseline: 1.0166x; 1.0004x over previous
#include <cuda_runtime.h>
#include <cstdint>

#define BB 2
#define CC 512
#define LL 2304
#define NH 8
#define HD 64
#define KT 64
#define NT (LL/KT)        // 36
#define MW 72             // mask words per row (2304/32)

// ---------------- scratch (__device__ globals; no allocs allowed) ----------
__device__ float    g_q[(size_t)BB*NH*LL*HD];   // tf32-rounded
__device__ float    g_k[(size_t)BB*NH*LL*HD];   // tf32-rounded
__device__ float    g_v[(size_t)BB*NH*LL*HD];   // tf32-rounded
__device__ float    g_att[(size_t)BB*CC*LL];
__device__ float    g_y[(size_t)BB*CC*LL];
__device__ float    g_xp[(size_t)BB*CC*LL];
__device__ unsigned g_mbits[(size_t)NH*LL*MW];

// ---------------- helpers ---------------------------------------------------
__device__ __forceinline__ uint32_t smem_u32(const void* p) {
    uint32_t a;
    asm("{ .reg .u64 t; cvta.to.shared.u64 t, %1; cvt.u32.u64 %0, t; }" : "=r"(a) : "l"(p));
    return a;
}
__device__ __forceinline__ uint32_t tf32b(float x) {
    uint32_t u; asm("cvt.rna.tf32.f32 %0, %1;" : "=r"(u) : "f"(x));
    return u;
}
__device__ __forceinline__ float rna(float x) { return __uint_as_float(tf32b(x)); }
__device__ __forceinline__ void mma8(float* c, const uint32_t* a, uint32_t b0, uint32_t b1) {
    asm volatile("mma.sync.aligned.m16n8k8.row.col.f32.tf32.tf32.f32 "
        "{%0,%1,%2,%3}, {%4,%5,%6,%7}, {%8,%9}, {%0,%1,%2,%3};"
        : "+f"(c[0]), "+f"(c[1]), "+f"(c[2]), "+f"(c[3])
        : "r"(a[0]), "r"(a[1]), "r"(a[2]), "r"(a[3]), "r"(b0), "r"(b1));
}
#define CP_ASYNC(dst, src) asm volatile("cp.async.cg.shared.global [%0], [%1], 16;" :: "r"(dst), "l"(src))
#define CP_COMMIT()        asm volatile("cp.async.commit_group;" ::: "memory")
#define CP_WAIT0()         asm volatile("cp.async.wait_group 0;" ::: "memory")

// ======================= attention kernel ===================================
#define OFF_Q   0                 // 256 x 68
#define OFF_K   17408             // 2 x 64 x 68
#define OFF_V   26112             // 2 x 64 x 68
#define OFF_P   34816             // 8 warps x 32 x 68
#define OFF_REL 52224             // 68
#define SM_FLOATS 52292
#define SM_BYTES (SM_FLOATS*4)

__global__ __launch_bounds__(256) void pack_kernel(const int* __restrict__ mask)
{
    size_t idx = (size_t)blockIdx.x * 256 + threadIdx.x;   // word index
    const int4* src = (const int4*)(mask + idx * 32);
    unsigned bits = 0;
    #pragma unroll
    for (int i = 0; i < 8; i++) {
        int4 v = src[i];
        bits |= (v.x ? 1u : 0u) << (i*4 + 0);
        bits |= (v.y ? 1u : 0u) << (i*4 + 1);
        bits |= (v.z ? 1u : 0u) << (i*4 + 2);
        bits |= (v.w ? 1u : 0u) << (i*4 + 3);
    }
    g_mbits[idx] = bits;
}

__global__ __launch_bounds__(256) void attn_kernel(const float* __restrict__ rel)
{
    extern __shared__ float sm[];
    const int tid = threadIdx.x, wid = tid >> 5, lane = tid & 31;
    const int lr = lane >> 2, lc = lane & 3;
    const int b = blockIdx.z, h = blockIdx.y;
    const int q0 = blockIdx.x * 256;
    const int wq = wid * 32;
    const size_t bh = (size_t)(b * NH + h) * LL;

    float* Qs = sm + OFF_Q;
    float* Pw = sm + OFF_P + wid * (32 * 68);
    float* srel = sm + OFF_REL;

    if (tid < 65) srel[tid] = rel[h * 65 + tid];

    // Q (already tf32-rounded) -> SMEM
    {
        const float4* qp = (const float4*)(g_q + (bh + q0) * HD);
        #pragma unroll
        for (int i = 0; i < 16; i++) {
            int fidx = i * 256 + tid;
            int row = fidx >> 4, c4 = (fidx & 15) * 4;
            float4 v = qp[fidx];
            float* d = Qs + row * 68 + c4;
            d[0] = v.x; d[1] = v.y; d[2] = v.z; d[3] = v.w;
        }
    }

    {
        const float* gk = g_k + bh * HD;
        const float* gv = g_v + bh * HD;
        uint32_t sk = smem_u32(sm + OFF_K), sv = smem_u32(sm + OFF_V);
        #pragma unroll
        for (int i = 0; i < 4; i++) {
            int fidx = i * 256 + tid;
            int row = fidx >> 4, c4 = (fidx & 15) * 4;
            uint32_t off = (uint32_t)(row * 68 + c4) * 4;
            CP_ASYNC(sk + off, gk + row * HD + c4);
            CP_ASYNC(sv + off, gv + row * HD + c4);
        }
        CP_COMMIT();
    }

    float oacc[2][8][4] = {};
    float lsum4[4] = {};
    const float rel0c = rel[h * 65 + 0], rel64c = rel[h * 65 + 64];

    for (int t = 0; t < NT; t++) {
        const int kt = t * KT;
        const int buf = t & 1;
        const uint32_t* Ks = (const uint32_t*)(sm + OFF_K + buf * (64 * 68));
        const uint32_t* Vs = (const uint32_t*)(sm + OFF_V + buf * (64 * 68));

        CP_WAIT0();
        __syncthreads();

        if (t + 1 < NT) {
            const float* gk = g_k + (bh + kt + KT) * HD;
            const float* gv = g_v + (bh + kt + KT) * HD;
            uint32_t sk = smem_u32(sm + OFF_K + (buf ^ 1) * (64 * 68));
            uint32_t sv = smem_u32(sm + OFF_V + (buf ^ 1) * (64 * 68));
            #pragma unroll
            for (int i = 0; i < 4; i++) {
                int fidx = i * 256 + tid;
                int row = fidx >> 4, c4 = (fidx & 15) * 4;
                uint32_t off = (uint32_t)(row * 68 + c4) * 4;
                CP_ASYNC(sk + off, gk + row * HD + c4);
                CP_ASYNC(sv + off, gv + row * HD + c4);
            }
            CP_COMMIT();
        }

        uint2 mwv[4];
        #pragma unroll
        for (int rr = 0; rr < 4; rr++) {
            int l = q0 + wq + (rr >> 1) * 16 + (rr & 1) * 8 + lr;
            mwv[rr] = *(const uint2*)(g_mbits + ((size_t)h * LL + l) * MW + 2 * t);
        }

        // ---- QK: fragments loaded as raw tf32 bits (no cvt) ----
        float sacc[2][8][4] = {};
        const uint32_t* Qb = (const uint32_t*)Qs;
        #pragma unroll
        for (int ks = 0; ks < 8; ks++) {
            uint32_t af[2][4];
            #pragma unroll
            for (int mt = 0; mt < 2; mt++) {
                const uint32_t* qb = Qb + (wq + mt * 16 + lr) * 68 + ks * 8 + lc;
                af[mt][0] = qb[0];
                af[mt][1] = qb[8 * 68];
                af[mt][2] = qb[4];
                af[mt][3] = qb[8 * 68 + 4];
            }
            #pragma unroll
            for (int j = 0; j < 8; j++) {
                const uint32_t* kb = Ks + (8 * j + lr) * 68 + ks * 8 + lc;
                uint32_t b0 = kb[0];
                uint32_t b1 = kb[4];
                mma8(sacc[0][j], af[0], b0, b1);
                mma8(sacc[1][j], af[1], b0, b1);
            }
        }

        // ---- softmax epilogue -> P (tf32 bits) in per-warp SMEM ----
        #pragma unroll
        for (int mt = 0; mt < 2; mt++) {
            #pragma unroll
            for (int rh = 0; rh < 2; rh++) {
                const int rowloc = mt * 16 + rh * 8 + lr;
                const int l = q0 + wq + rowloc;
                const uint2 mw = mwv[mt * 2 + rh];
                const bool hi = (l - kt) >= 96;
                const bool lo = (kt - l) >= 33;
                float rsum = 0.f;
                #pragma unroll
                for (int j = 0; j < 8; j++) {
                    const int k0 = 8 * j + 2 * lc;
                    float v0 = sacc[mt][j][rh * 2 + 0];
                    float v1 = sacc[mt][j][rh * 2 + 1];
                    float b0v, b1v;
                    if (hi)      { b0v = rel64c; b1v = rel64c; }
                    else if (lo) { b0v = rel0c;  b1v = rel0c;  }
                    else {
                        int e = l - kt - k0 + 32;
                        int e0 = e < 0 ? 0 : (e > 64 ? 64 : e);
                        int e1 = e - 1; e1 = e1 < 0 ? 0 : (e1 > 64 ? 64 : e1);
                        b0v = srel[e0]; b1v = srel[e1];
                    }
                    unsigned mword = (j < 4) ? mw.x : mw.y;
                    float p0 = ((mword >> (k0 & 31)) & 1u)       ? __expf(fmaf(v0, 0.125f, b0v)) : 0.f;
                    float p1 = ((mword >> ((k0 + 1) & 31)) & 1u) ? __expf(fmaf(v1, 0.125f, b1v)) : 0.f;
                    rsum += p0 + p1;
                    uint2 pp; pp.x = tf32b(p0); pp.y = tf32b(p1);
                    *(uint2*)(Pw + rowloc * 68 + k0) = pp;
                }
                rsum += __shfl_xor_sync(0xffffffffu, rsum, 1);
                rsum += __shfl_xor_sync(0xffffffffu, rsum, 2);
                lsum4[mt * 2 + rh] += rsum;
            }
        }
        __syncwarp();

        // ---- PV: P bits + V bits straight from SMEM (no cvt) ----
        #pragma unroll
        for (int ks = 0; ks < 8; ks++) {
            uint32_t af[2][4];
            #pragma unroll
            for (int mt = 0; mt < 2; mt++) {
                const uint32_t* pb = (const uint32_t*)(Pw + (mt * 16 + lr) * 68 + ks * 8 + lc);
                af[mt][0] = pb[0];
                af[mt][1] = pb[8 * 68];
                af[mt][2] = pb[4];
                af[mt][3] = pb[8 * 68 + 4];
            }
            #pragma unroll
            for (int j = 0; j < 8; j++) {
                const uint32_t* vb = Vs + (ks * 8 + lc) * 68 + 8 * j + lr;
                uint32_t b0 = vb[0];
                uint32_t b1 = vb[4 * 68];
                mma8(oacc[0][j], af[0], b0, b1);
                mma8(oacc[1][j], af[1], b0, b1);
            }
        }
        __syncwarp();
    }

    #pragma unroll
    for (int mt = 0; mt < 2; mt++) {
        #pragma unroll
        for (int rh = 0; rh < 2; rh++) {
            const int rowloc = mt * 16 + rh * 8 + lr;
            const float inv = 1.f / lsum4[mt * 2 + rh];
            #pragma unroll
            for (int j = 0; j < 8; j++) {
                float2 o;
                o.x = oacc[mt][j][rh * 2 + 0] * inv;
                o.y = oacc[mt][j][rh * 2 + 1] * inv;
                *(float2*)(Pw + rowloc * 68 + 8 * j + 2 * lc) = o;
            }
        }
    }
    __syncwarp();
    {
        const int l = q0 + wq + lane;
        float* ob = g_att + ((size_t)b * CC + h * 64) * LL + l;
        #pragma unroll
        for (int dd = 0; dd < 64; dd++)
            ob[(size_t)dd * LL] = Pw[lane * 68 + dd];
    }
}

// ======================= tf32 mma GEMMs, cp.async pipelined =================
#define XS_STRIDE 264
#define WS_STRIDE 68
#define PX_STAGE  16896               // 64 x 264 floats
#define PW_STAGE  4352                // 64 x 68 floats
#define P_X0 0
#define P_X1 PX_STAGE
#define P_W0 (2*PX_STAGE)
#define P_W1 (P_W0 + PW_STAGE)
#define P_TOTF (P_W0 + 2*PW_STAGE)    // 42496 floats
#define P_BYTES (P_TOTF*4)            // 169984 bytes

__global__ __launch_bounds__(256) void add_pos_kernel(
    const float* __restrict__ x, const float* __restrict__ pos)
{
    size_t i = (size_t)blockIdx.x * 256 + threadIdx.x;       // float4 index
    const size_t n4 = (size_t)CC * LL / 4;
    float4 xv = ((const float4*)x)[i];
    float4 pv = ((const float4*)pos)[i % n4];
    ((float4*)g_xp)[i] = make_float4(xv.x + pv.x, xv.y + pv.y, xv.z + pv.z, xv.w + pv.w);
}

__device__ __forceinline__ void gemm_prefetch(
    float* sm, int stg, int tid, const float* __restrict__ src, int l0,
    const float* __restrict__ W, int oc0, int kt)
{
    uint32_t xs = smem_u32(sm + (stg ? P_X1 : P_X0));
    uint32_t ws = smem_u32(sm + (stg ? P_W1 : P_W0));
    #pragma unroll
    for (int i = 0; i < 16; i++) {
        int fidx = i * 256 + tid;
        int c = fidx >> 6, l4 = (fidx & 63) * 4;
        CP_ASYNC(xs + (uint32_t)(c * XS_STRIDE + l4) * 4, src + (size_t)(kt + c) * LL + l0 + l4);
    }
    #pragma unroll
    for (int i = 0; i < 4; i++) {
        int fidx = i * 256 + tid;
        int oc = fidx >> 4, c4 = (fidx & 15) * 4;
        CP_ASYNC(ws + (uint32_t)(oc * WS_STRIDE + c4) * 4, W + (size_t)(oc0 + oc) * CC + kt + c4);
    }
    CP_COMMIT();
}

__device__ __forceinline__ void gemm_chunk(
    const float* __restrict__ sm, int buf, int wid, int lr, int lc,
    float acc[2][8][4])
{
    const float* Xs = sm + (buf ? P_X1 : P_X0);
    const float* Wr = sm + (buf ? P_W1 : P_W0);
    #pragma unroll
    for (int ks = 0; ks < 8; ks++) {
        uint32_t ahi[2][4], alo[2][4];
        #pragma unroll
        for (int mt = 0; mt < 2; mt++) {
            const float* ab = Xs + (ks * 8 + lc) * XS_STRIDE + wid * 32 + mt * 16 + lr;
            float a0 = ab[0], a1 = ab[8], a2 = ab[4 * XS_STRIDE], a3 = ab[4 * XS_STRIDE + 8];
            ahi[mt][0] = tf32b(a0); alo[mt][0] = tf32b(a0 - __uint_as_float(ahi[mt][0]));
            ahi[mt][1] = tf32b(a1); alo[mt][1] = tf32b(a1 - __uint_as_float(ahi[mt][1]));
            ahi[mt][2] = tf32b(a2); alo[mt][2] = tf32b(a2 - __uint_as_float(ahi[mt][2]));
            ahi[mt][3] = tf32b(a3); alo[mt][3] = tf32b(a3 - __uint_as_float(ahi[mt][3]));
        }
        #pragma unroll
        for (int j = 0; j < 8; j++) {
            const float* wr = Wr + (8 * j + lr) * WS_STRIDE + ks * 8 + lc;
            float w0 = wr[0], w1 = wr[4];
            uint32_t bh0 = tf32b(w0), bh1 = tf32b(w1);
            uint32_t bl0 = tf32b(w0 - __uint_as_float(bh0));
            uint32_t bl1 = tf32b(w1 - __uint_as_float(bh1));
            mma8(acc[0][j], ahi[0], bh0, bh1);
            mma8(acc[1][j], ahi[1], bh0, bh1);
            mma8(acc[0][j], alo[0], bh0, bh1);
            mma8(acc[1][j], alo[1], bh0, bh1);
            mma8(acc[0][j], ahi[0], bl0, bl1);
            mma8(acc[1][j], ahi[1], bl0, bl1);
        }
    }
}

// out[b,h,l,d] = tf32_round( sum_c xp[b,c,l] * W[h*64+d, c] + bias )
__global__ __launch_bounds__(256) void gemm_qkv_mma(
    const float* __restrict__ Wq, const float* __restrict__ bq,
    const float* __restrict__ Wk, const float* __restrict__ bk,
    const float* __restrict__ Wv, const float* __restrict__ bv)
{
    extern __shared__ float sm[];
    const int tid = threadIdx.x, wid = tid >> 5, lane = tid & 31;
    const int lr = lane >> 2, lc = lane & 3;
    const int l0 = blockIdx.x * 256;
    const int h = blockIdx.y;
    const int zz = blockIdx.z;
    const int b = zz / 3, proj = zz % 3;
    const float* W    = (proj == 0) ? Wq : (proj == 1) ? Wk : Wv;
    const float* bias = (proj == 0) ? bq : (proj == 1) ? bk : bv;
    float* out        = (proj == 0) ? g_q : (proj == 1) ? g_k : g_v;
    const int oc0 = h * 64;
    const float* src = g_xp + (size_t)b * CC * LL;

    float acc[2][8][4] = {};

    gemm_prefetch(sm, 0, tid, src, l0, W, oc0, 0);
    #pragma unroll 1
    for (int ci = 0; ci < CC / 64; ci++) {
        const int buf = ci & 1;
        CP_WAIT0();
        __syncthreads();
        if (ci + 1 < CC / 64)
            gemm_prefetch(sm, buf ^ 1, tid, src, l0, W, oc0, (ci + 1) * 64);
        gemm_chunk(sm, buf, wid, lr, lc, acc);
    }

    #pragma unroll
    for (int j = 0; j < 8; j++) {
        float2 bv2 = *(const float2*)(bias + oc0 + 8 * j + 2 * lc);
        #pragma unroll
        for (int mt = 0; mt < 2; mt++) {
            int l = l0 + wid * 32 + mt * 16 + lr;
            size_t rb = ((size_t)(b * NH + h) * LL + l) * HD + 8 * j + 2 * lc;
            float2 r0 = make_float2(rna(acc[mt][j][0] + bv2.x), rna(acc[mt][j][1] + bv2.y));
            float2 r1 = make_float2(rna(acc[mt][j][2] + bv2.x), rna(acc[mt][j][3] + bv2.y));
            *(float2*)(out + rb) = r0;
            *(float2*)(out + rb + (size_t)8 * HD) = r1;
        }
    }
}

// y[b,oc,l] = sum_c Wo[oc,c]*att[b,c,l] + bo[oc] + x[b,oc,l]
__global__ __launch_bounds__(256) void gemm_proj_mma(
    const float* __restrict__ W, const float* __restrict__ bias,
    const float* __restrict__ xres)
{
    extern __shared__ float sm[];
    const int tid = threadIdx.x, wid = tid >> 5, lane = tid & 31;
    const int lr = lane >> 2, lc = lane & 3;
    const int l0 = blockIdx.x * 256;
    const int oc0 = blockIdx.y * 64;
    const int b = blockIdx.z;
    const float* src = g_att + (size_t)b * CC * LL;

    float acc[2][8][4] = {};

    gemm_prefetch(sm, 0, tid, src, l0, W, oc0, 0);
    #pragma unroll 1
    for (int ci = 0; ci < CC / 64; ci++) {
        const int buf = ci & 1;
        CP_WAIT0();
        __syncthreads();
        if (ci + 1 < CC / 64)
            gemm_prefetch(sm, buf ^ 1, tid, src, l0, W, oc0, (ci + 1) * 64);
        gemm_chunk(sm, buf, wid, lr, lc, acc);
    }

    __syncthreads();
    float* Pw = sm + wid * (32 * 66);
    #pragma unroll
    for (int j = 0; j < 8; j++) {
        #pragma unroll
        for (int mt = 0; mt < 2; mt++) {
            int r0 = mt * 16 + lr;
            *(float2*)(Pw + r0 * 66 + 8 * j + 2 * lc) = make_float2(acc[mt][j][0], acc[mt][j][1]);
            *(float2*)(Pw + (r0 + 8) * 66 + 8 * j + 2 * lc) = make_float2(acc[mt][j][2], acc[mt][j][3]);
        }
    }
    __syncwarp();
    {
        const int l = l0 + wid * 32 + lane;
        #pragma unroll 8
        for (int dd = 0; dd < 64; dd++) {
            int oc = oc0 + dd;
            size_t gidx = ((size_t)(b * CC + oc)) * LL + l;
            g_y[gidx] = Pw[lane * 66 + dd] + bias[oc] + xres[gidx];
        }
    }
}

// ---------------------------------------------------------------------------
// LayerNorm: 32 pixels x 512 channels per CTA, coalesced over l.
// ---------------------------------------------------------------------------
__global__ __launch_bounds__(256) void ln_kernel(
    const float* __restrict__ gamma, const float* __restrict__ beta,
    float* __restrict__ out)
{
    const int w = threadIdx.x >> 5, lane = threadIdx.x & 31;
    const int p0 = blockIdx.x * 32;
    const int b = p0 / LL;
    const int l = p0 % LL + lane;
    const float* yb = g_y + (size_t)b * CC * LL;

    float vals[64];
    float s = 0.f, s2 = 0.f;
    #pragma unroll
    for (int i = 0; i < 64; i++) {
        float v = yb[(size_t)(w * 64 + i) * LL + l];
        vals[i] = v; s += v; s2 += v * v;
    }
    __shared__ float ss[8][32], ss2[8][32];
    ss[w][lane] = s; ss2[w][lane] = s2;
    __syncthreads();
    float st = 0.f, st2 = 0.f;
    #pragma unroll
    for (int i = 0; i < 8; i++) { st += ss[i][lane]; st2 += ss2[i][lane]; }
    float mean = st * (1.f / CC);
    float var = st2 * (1.f / CC) - mean * mean;
    float rs = rsqrtf(var + 1e-5f);

    float* ob = out + (size_t)b * CC * LL;
    #pragma unroll
    for (int i = 0; i < 64; i++) {
        int c = w * 64 + i;
        ob[(size_t)c * LL + l] = (vals[i] - mean) * rs * gamma[c] + beta[c];
    }
}

// ---------------------------------------------------------------------------
extern "C" void kernel_launch(void* const* d_in, const int* in_sizes, int n_in,
                              void* d_out, int out_size)
{
    const float* x    = (const float*)d_in[0];
    const int*   mask = (const int*)d_in[1];
    const float* pos  = (const float*)d_in[2];
    const float* Wq = (const float*)d_in[3];
    const float* bq = (const float*)d_in[4];
    const float* Wk = (const float*)d_in[5];
    const float* bk = (const float*)d_in[6];
    const float* Wv = (const float*)d_in[7];
    const float* bv = (const float*)d_in[8];
    const float* Wo = (const float*)d_in[9];
    const float* bo = (const float*)d_in[10];
    const float* rel = (const float*)d_in[11];
    const float* gam = (const float*)d_in[12];
    const float* bet = (const float*)d_in[13];
    float* out = (float*)d_out;

    static bool attr_set = false;
    if (!attr_set) {
        cudaFuncSetAttribute(attn_kernel, cudaFuncAttributeMaxDynamicSharedMemorySize, SM_BYTES);
        cudaFuncSetAttribute(gemm_qkv_mma, cudaFuncAttributeMaxDynamicSharedMemorySize, P_BYTES);
        cudaFuncSetAttribute(gemm_proj_mma, cudaFuncAttributeMaxDynamicSharedMemorySize, P_BYTES);
        attr_set = true;
    }

    add_pos_kernel<<<(BB * CC * LL) / 4 / 256, 256>>>(x, pos);
    gemm_qkv_mma<<<dim3(LL / 256, NH, BB * 3), 256, P_BYTES>>>(Wq, bq, Wk, bk, Wv, bv);
    pack_kernel<<<(NH * LL * MW) / 256, 256>>>(mask);
    attn_kernel<<<dim3(LL / 256, NH, BB), 256, SM_BYTES>>>(rel);
    gemm_proj_mma<<<dim3(LL / 256, CC / 64, BB), 256, P_BYTES>>>(Wo, bo, x);
    ln_kernel<<<(BB * LL) / 32, 256>>>(gam, bet, out);
}

// round 11
// speedup vs baseline: 1.0940x; 1.0761x over previous
#include <cuda_runtime.h>
#include <cstdint>

#define BB 2
#define CC 512
#define LL 2304
#define NH 8
#define HD 64
#define KT 64
#define NT (LL/KT)        // 36
#define MW 72             // mask words per row (2304/32)

// ---------------- scratch (__device__ globals; no allocs allowed) ----------
__device__ float    g_q[(size_t)BB*NH*LL*HD];   // tf32-rounded
__device__ float    g_k[(size_t)BB*NH*LL*HD];   // tf32-rounded
__device__ float    g_v[(size_t)BB*NH*LL*HD];   // tf32-rounded
__device__ float    g_att[(size_t)BB*CC*LL];
__device__ float    g_y[(size_t)BB*CC*LL];
__device__ float    g_xp[(size_t)BB*CC*LL];
__device__ unsigned g_mbits[(size_t)NH*LL*MW];

// ---------------- helpers ---------------------------------------------------
__device__ __forceinline__ uint32_t smem_u32(const void* p) {
    uint32_t a;
    asm("{ .reg .u64 t; cvta.to.shared.u64 t, %1; cvt.u32.u64 %0, t; }" : "=r"(a) : "l"(p));
    return a;
}
__device__ __forceinline__ uint32_t tf32b(float x) {
    uint32_t u; asm("cvt.rna.tf32.f32 %0, %1;" : "=r"(u) : "f"(x));
    return u;
}
__device__ __forceinline__ float rna(float x) { return __uint_as_float(tf32b(x)); }
__device__ __forceinline__ void mma8(float* c, const uint32_t* a, uint32_t b0, uint32_t b1) {
    asm volatile("mma.sync.aligned.m16n8k8.row.col.f32.tf32.tf32.f32 "
        "{%0,%1,%2,%3}, {%4,%5,%6,%7}, {%8,%9}, {%0,%1,%2,%3};"
        : "+f"(c[0]), "+f"(c[1]), "+f"(c[2]), "+f"(c[3])
        : "r"(a[0]), "r"(a[1]), "r"(a[2]), "r"(a[3]), "r"(b0), "r"(b1));
}
#define CP_ASYNC(dst, src) asm volatile("cp.async.cg.shared.global [%0], [%1], 16;" :: "r"(dst), "l"(src))
#define CP_COMMIT()        asm volatile("cp.async.commit_group;" ::: "memory")
#define CP_WAIT0()         asm volatile("cp.async.wait_group 0;" ::: "memory")

// ======================= attention kernel ===================================
// 128 threads / 128 queries per CTA; SMEM ~104.7KB => 2 CTAs per SM.
// Region A (8704 floats) stages Q (coalesced load -> register fragments),
// then is reused as the per-warp P buffer.
#define A_OFF_A   0                   // 8704 floats: Q staging, then P (4 warps x 32 x 68)
#define A_OFF_K   8704                // 2 x 64 x 68
#define A_OFF_V   17408               // 2 x 64 x 68
#define A_OFF_REL 26112               // 68
#define A_FLOATS  26180
#define A_BYTES   (A_FLOATS*4)        // 104720 bytes

__global__ __launch_bounds__(256) void pack_kernel(const int* __restrict__ mask)
{
    size_t idx = (size_t)blockIdx.x * 256 + threadIdx.x;   // word index
    const int4* src = (const int4*)(mask + idx * 32);
    unsigned bits = 0;
    #pragma unroll
    for (int i = 0; i < 8; i++) {
        int4 v = src[i];
        bits |= (v.x ? 1u : 0u) << (i*4 + 0);
        bits |= (v.y ? 1u : 0u) << (i*4 + 1);
        bits |= (v.z ? 1u : 0u) << (i*4 + 2);
        bits |= (v.w ? 1u : 0u) << (i*4 + 3);
    }
    g_mbits[idx] = bits;
}

__global__ __launch_bounds__(128) void attn_kernel(const float* __restrict__ rel)
{
    extern __shared__ float sm[];
    const int tid = threadIdx.x, wid = tid >> 5, lane = tid & 31;
    const int lr = lane >> 2, lc = lane & 3;
    const int b = blockIdx.z, h = blockIdx.y;
    const int q0 = blockIdx.x * 128;
    const int wq = wid * 32;
    const size_t bh = (size_t)(b * NH + h) * LL;

    float* Acm = sm + A_OFF_A;                 // Q staging / P region
    float* Pw  = Acm + wid * (32 * 68);
    float* srel = sm + A_OFF_REL;

    if (tid < 65) srel[tid] = rel[h * 65 + tid];

    // Q (tf32-rounded) -> staging SMEM, coalesced (128 rows x 16 float4)
    {
        const float4* qp = (const float4*)(g_q + (bh + q0) * HD);
        #pragma unroll
        for (int i = 0; i < 16; i++) {
            int fidx = i * 128 + tid;
            int row = fidx >> 4, c4 = (fidx & 15) * 4;
            float4 v = qp[fidx];
            float* d = Acm + row * 68 + c4;
            d[0] = v.x; d[1] = v.y; d[2] = v.z; d[3] = v.w;
        }
    }

    // prefetch K/V tile 0 (1024 float4 each; 8 iters with 128 threads)
    {
        const float* gk = g_k + bh * HD;
        const float* gv = g_v + bh * HD;
        uint32_t sk = smem_u32(sm + A_OFF_K), sv = smem_u32(sm + A_OFF_V);
        #pragma unroll
        for (int i = 0; i < 8; i++) {
            int fidx = i * 128 + tid;
            int row = fidx >> 4, c4 = (fidx & 15) * 4;
            uint32_t off = (uint32_t)(row * 68 + c4) * 4;
            CP_ASYNC(sk + off, gk + row * HD + c4);
            CP_ASYNC(sv + off, gv + row * HD + c4);
        }
        CP_COMMIT();
    }
    __syncthreads();   // Q staging visible to all warps

    // extract Q fragments to registers (reused across all 36 tiles)
    uint32_t qreg[2][8][4];
    {
        const uint32_t* Qb = (const uint32_t*)Acm;
        #pragma unroll
        for (int mt = 0; mt < 2; mt++) {
            #pragma unroll
            for (int ks = 0; ks < 8; ks++) {
                const uint32_t* qb = Qb + (wq + mt * 16 + lr) * 68 + ks * 8 + lc;
                qreg[mt][ks][0] = qb[0];
                qreg[mt][ks][1] = qb[8 * 68];
                qreg[mt][ks][2] = qb[4];
                qreg[mt][ks][3] = qb[8 * 68 + 4];
            }
        }
    }

    float oacc[2][8][4] = {};
    float lsum4[4] = {};
    const float rel0c = rel[h * 65 + 0], rel64c = rel[h * 65 + 64];

    for (int t = 0; t < NT; t++) {
        const int kt = t * KT;
        const int buf = t & 1;
        const uint32_t* Ks = (const uint32_t*)(sm + A_OFF_K + buf * (64 * 68));
        const uint32_t* Vs = (const uint32_t*)(sm + A_OFF_V + buf * (64 * 68));

        CP_WAIT0();
        __syncthreads();   // (also guarantees Q extraction done before first P write)

        if (t + 1 < NT) {
            const float* gk = g_k + (bh + kt + KT) * HD;
            const float* gv = g_v + (bh + kt + KT) * HD;
            uint32_t sk = smem_u32(sm + A_OFF_K + (buf ^ 1) * (64 * 68));
            uint32_t sv = smem_u32(sm + A_OFF_V + (buf ^ 1) * (64 * 68));
            #pragma unroll
            for (int i = 0; i < 8; i++) {
                int fidx = i * 128 + tid;
                int row = fidx >> 4, c4 = (fidx & 15) * 4;
                uint32_t off = (uint32_t)(row * 68 + c4) * 4;
                CP_ASYNC(sk + off, gk + row * HD + c4);
                CP_ASYNC(sv + off, gv + row * HD + c4);
            }
            CP_COMMIT();
        }

        uint2 mwv[4];
        #pragma unroll
        for (int rr = 0; rr < 4; rr++) {
            int l = q0 + wq + (rr >> 1) * 16 + (rr & 1) * 8 + lr;
            mwv[rr] = *(const uint2*)(g_mbits + ((size_t)h * LL + l) * MW + 2 * t);
        }

        // ---- QK: A-fragments from registers, K bits from SMEM ----
        float sacc[2][8][4] = {};
        #pragma unroll
        for (int ks = 0; ks < 8; ks++) {
            #pragma unroll
            for (int j = 0; j < 8; j++) {
                const uint32_t* kb = Ks + (8 * j + lr) * 68 + ks * 8 + lc;
                uint32_t b0 = kb[0];
                uint32_t b1 = kb[4];
                mma8(sacc[0][j], qreg[0][ks], b0, b1);
                mma8(sacc[1][j], qreg[1][ks], b0, b1);
            }
        }

        // ---- softmax epilogue -> P (tf32 bits) in per-warp SMEM ----
        #pragma unroll
        for (int mt = 0; mt < 2; mt++) {
            #pragma unroll
            for (int rh = 0; rh < 2; rh++) {
                const int rowloc = mt * 16 + rh * 8 + lr;
                const int l = q0 + wq + rowloc;
                const uint2 mw = mwv[mt * 2 + rh];
                const bool hi = (l - kt) >= 96;
                const bool lo = (kt - l) >= 33;
                float rsum = 0.f;
                #pragma unroll
                for (int j = 0; j < 8; j++) {
                    const int k0 = 8 * j + 2 * lc;
                    float v0 = sacc[mt][j][rh * 2 + 0];
                    float v1 = sacc[mt][j][rh * 2 + 1];
                    float b0v, b1v;
                    if (hi)      { b0v = rel64c; b1v = rel64c; }
                    else if (lo) { b0v = rel0c;  b1v = rel0c;  }
                    else {
                        int e = l - kt - k0 + 32;
                        int e0 = e < 0 ? 0 : (e > 64 ? 64 : e);
                        int e1 = e - 1; e1 = e1 < 0 ? 0 : (e1 > 64 ? 64 : e1);
                        b0v = srel[e0]; b1v = srel[e1];
                    }
                    unsigned mword = (j < 4) ? mw.x : mw.y;
                    float p0 = ((mword >> (k0 & 31)) & 1u)       ? __expf(fmaf(v0, 0.125f, b0v)) : 0.f;
                    float p1 = ((mword >> ((k0 + 1) & 31)) & 1u) ? __expf(fmaf(v1, 0.125f, b1v)) : 0.f;
                    rsum += p0 + p1;
                    uint2 pp; pp.x = tf32b(p0); pp.y = tf32b(p1);
                    *(uint2*)(Pw + rowloc * 68 + k0) = pp;
                }
                rsum += __shfl_xor_sync(0xffffffffu, rsum, 1);
                rsum += __shfl_xor_sync(0xffffffffu, rsum, 2);
                lsum4[mt * 2 + rh] += rsum;
            }
        }
        __syncwarp();

        // ---- PV: P bits + V bits straight from SMEM ----
        #pragma unroll
        for (int ks = 0; ks < 8; ks++) {
            uint32_t af[2][4];
            #pragma unroll
            for (int mt = 0; mt < 2; mt++) {
                const uint32_t* pb = (const uint32_t*)(Pw + (mt * 16 + lr) * 68 + ks * 8 + lc);
                af[mt][0] = pb[0];
                af[mt][1] = pb[8 * 68];
                af[mt][2] = pb[4];
                af[mt][3] = pb[8 * 68 + 4];
            }
            #pragma unroll
            for (int j = 0; j < 8; j++) {
                const uint32_t* vb = Vs + (ks * 8 + lc) * 68 + 8 * j + lr;
                uint32_t b0 = vb[0];
                uint32_t b1 = vb[4 * 68];
                mma8(oacc[0][j], af[0], b0, b1);
                mma8(oacc[1][j], af[1], b0, b1);
            }
        }
        __syncwarp();
    }

    #pragma unroll
    for (int mt = 0; mt < 2; mt++) {
        #pragma unroll
        for (int rh = 0; rh < 2; rh++) {
            const int rowloc = mt * 16 + rh * 8 + lr;
            const float inv = 1.f / lsum4[mt * 2 + rh];
            #pragma unroll
            for (int j = 0; j < 8; j++) {
                float2 o;
                o.x = oacc[mt][j][rh * 2 + 0] * inv;
                o.y = oacc[mt][j][rh * 2 + 1] * inv;
                *(float2*)(Pw + rowloc * 68 + 8 * j + 2 * lc) = o;
            }
        }
    }
    __syncwarp();
    {
        const int l = q0 + wq + lane;
        float* ob = g_att + ((size_t)b * CC + h * 64) * LL + l;
        #pragma unroll
        for (int dd = 0; dd < 64; dd++)
            ob[(size_t)dd * LL] = Pw[lane * 68 + dd];
    }
}

// ======================= tf32 mma GEMMs, cp.async pipelined =================
#define XS_STRIDE 264
#define WS_STRIDE 68
#define PX_STAGE  16896               // 64 x 264 floats
#define PW_STAGE  4352                // 64 x 68 floats
#define P_X0 0
#define P_X1 PX_STAGE
#define P_W0 (2*PX_STAGE)
#define P_W1 (P_W0 + PW_STAGE)
#define P_TOTF (P_W0 + 2*PW_STAGE)    // 42496 floats
#define P_BYTES (P_TOTF*4)            // 169984 bytes

__global__ __launch_bounds__(256) void add_pos_kernel(
    const float* __restrict__ x, const float* __restrict__ pos)
{
    size_t i = (size_t)blockIdx.x * 256 + threadIdx.x;       // float4 index
    const size_t n4 = (size_t)CC * LL / 4;
    float4 xv = ((const float4*)x)[i];
    float4 pv = ((const float4*)pos)[i % n4];
    ((float4*)g_xp)[i] = make_float4(xv.x + pv.x, xv.y + pv.y, xv.z + pv.z, xv.w + pv.w);
}

__device__ __forceinline__ void gemm_prefetch(
    float* sm, int stg, int tid, const float* __restrict__ src, int l0,
    const float* __restrict__ W, int oc0, int kt)
{
    uint32_t xs = smem_u32(sm + (stg ? P_X1 : P_X0));
    uint32_t ws = smem_u32(sm + (stg ? P_W1 : P_W0));
    #pragma unroll
    for (int i = 0; i < 16; i++) {
        int fidx = i * 256 + tid;
        int c = fidx >> 6, l4 = (fidx & 63) * 4;
        CP_ASYNC(xs + (uint32_t)(c * XS_STRIDE + l4) * 4, src + (size_t)(kt + c) * LL + l0 + l4);
    }
    #pragma unroll
    for (int i = 0; i < 4; i++) {
        int fidx = i * 256 + tid;
        int oc = fidx >> 4, c4 = (fidx & 15) * 4;
        CP_ASYNC(ws + (uint32_t)(oc * WS_STRIDE + c4) * 4, W + (size_t)(oc0 + oc) * CC + kt + c4);
    }
    CP_COMMIT();
}

__device__ __forceinline__ void gemm_chunk(
    const float* __restrict__ sm, int buf, int wid, int lr, int lc,
    float acc[2][8][4])
{
    const float* Xs = sm + (buf ? P_X1 : P_X0);
    const float* Wr = sm + (buf ? P_W1 : P_W0);
    #pragma unroll
    for (int ks = 0; ks < 8; ks++) {
        uint32_t ahi[2][4], alo[2][4];
        #pragma unroll
        for (int mt = 0; mt < 2; mt++) {
            const float* ab = Xs + (ks * 8 + lc) * XS_STRIDE + wid * 32 + mt * 16 + lr;
            float a0 = ab[0], a1 = ab[8], a2 = ab[4 * XS_STRIDE], a3 = ab[4 * XS_STRIDE + 8];
            ahi[mt][0] = tf32b(a0); alo[mt][0] = tf32b(a0 - __uint_as_float(ahi[mt][0]));
            ahi[mt][1] = tf32b(a1); alo[mt][1] = tf32b(a1 - __uint_as_float(ahi[mt][1]));
            ahi[mt][2] = tf32b(a2); alo[mt][2] = tf32b(a2 - __uint_as_float(ahi[mt][2]));
            ahi[mt][3] = tf32b(a3); alo[mt][3] = tf32b(a3 - __uint_as_float(ahi[mt][3]));
        }
        #pragma unroll
        for (int j = 0; j < 8; j++) {
            const float* wr = Wr + (8 * j + lr) * WS_STRIDE + ks * 8 + lc;
            float w0 = wr[0], w1 = wr[4];
            uint32_t bh0 = tf32b(w0), bh1 = tf32b(w1);
            uint32_t bl0 = tf32b(w0 - __uint_as_float(bh0));
            uint32_t bl1 = tf32b(w1 - __uint_as_float(bh1));
            mma8(acc[0][j], ahi[0], bh0, bh1);
            mma8(acc[1][j], ahi[1], bh0, bh1);
            mma8(acc[0][j], alo[0], bh0, bh1);
            mma8(acc[1][j], alo[1], bh0, bh1);
            mma8(acc[0][j], ahi[0], bl0, bl1);
            mma8(acc[1][j], ahi[1], bl0, bl1);
        }
    }
}

// out[b,h,l,d] = tf32_round( sum_c xp[b,c,l] * W[h*64+d, c] + bias )
__global__ __launch_bounds__(256) void gemm_qkv_mma(
    const float* __restrict__ Wq, const float* __restrict__ bq,
    const float* __restrict__ Wk, const float* __restrict__ bk,
    const float* __restrict__ Wv, const float* __restrict__ bv)
{
    extern __shared__ float sm[];
    const int tid = threadIdx.x, wid = tid >> 5, lane = tid & 31;
    const int lr = lane >> 2, lc = lane & 3;
    const int l0 = blockIdx.x * 256;
    const int h = blockIdx.y;
    const int zz = blockIdx.z;
    const int b = zz / 3, proj = zz % 3;
    const float* W    = (proj == 0) ? Wq : (proj == 1) ? Wk : Wv;
    const float* bias = (proj == 0) ? bq : (proj == 1) ? bk : bv;
    float* out        = (proj == 0) ? g_q : (proj == 1) ? g_k : g_v;
    const int oc0 = h * 64;
    const float* src = g_xp + (size_t)b * CC * LL;

    float acc[2][8][4] = {};

    gemm_prefetch(sm, 0, tid, src, l0, W, oc0, 0);
    #pragma unroll 1
    for (int ci = 0; ci < CC / 64; ci++) {
        const int buf = ci & 1;
        CP_WAIT0();
        __syncthreads();
        if (ci + 1 < CC / 64)
            gemm_prefetch(sm, buf ^ 1, tid, src, l0, W, oc0, (ci + 1) * 64);
        gemm_chunk(sm, buf, wid, lr, lc, acc);
    }

    #pragma unroll
    for (int j = 0; j < 8; j++) {
        float2 bv2 = *(const float2*)(bias + oc0 + 8 * j + 2 * lc);
        #pragma unroll
        for (int mt = 0; mt < 2; mt++) {
            int l = l0 + wid * 32 + mt * 16 + lr;
            size_t rb = ((size_t)(b * NH + h) * LL + l) * HD + 8 * j + 2 * lc;
            float2 r0 = make_float2(rna(acc[mt][j][0] + bv2.x), rna(acc[mt][j][1] + bv2.y));
            float2 r1 = make_float2(rna(acc[mt][j][2] + bv2.x), rna(acc[mt][j][3] + bv2.y));
            *(float2*)(out + rb) = r0;
            *(float2*)(out + rb + (size_t)8 * HD) = r1;
        }
    }
}

// y[b,oc,l] = sum_c Wo[oc,c]*att[b,c,l] + bo[oc] + x[b,oc,l]
__global__ __launch_bounds__(256) void gemm_proj_mma(
    const float* __restrict__ W, const float* __restrict__ bias,
    const float* __restrict__ xres)
{
    extern __shared__ float sm[];
    const int tid = threadIdx.x, wid = tid >> 5, lane = tid & 31;
    const int lr = lane >> 2, lc = lane & 3;
    const int l0 = blockIdx.x * 256;
    const int oc0 = blockIdx.y * 64;
    const int b = blockIdx.z;
    const float* src = g_att + (size_t)b * CC * LL;

    float acc[2][8][4] = {};

    gemm_prefetch(sm, 0, tid, src, l0, W, oc0, 0);
    #pragma unroll 1
    for (int ci = 0; ci < CC / 64; ci++) {
        const int buf = ci & 1;
        CP_WAIT0();
        __syncthreads();
        if (ci + 1 < CC / 64)
            gemm_prefetch(sm, buf ^ 1, tid, src, l0, W, oc0, (ci + 1) * 64);
        gemm_chunk(sm, buf, wid, lr, lc, acc);
    }

    __syncthreads();
    float* Pw = sm + wid * (32 * 66);
    #pragma unroll
    for (int j = 0; j < 8; j++) {
        #pragma unroll
        for (int mt = 0; mt < 2; mt++) {
            int r0 = mt * 16 + lr;
            *(float2*)(Pw + r0 * 66 + 8 * j + 2 * lc) = make_float2(acc[mt][j][0], acc[mt][j][1]);
            *(float2*)(Pw + (r0 + 8) * 66 + 8 * j + 2 * lc) = make_float2(acc[mt][j][2], acc[mt][j][3]);
        }
    }
    __syncwarp();
    {
        const int l = l0 + wid * 32 + lane;
        #pragma unroll 8
        for (int dd = 0; dd < 64; dd++) {
            int oc = oc0 + dd;
            size_t gidx = ((size_t)(b * CC + oc)) * LL + l;
            g_y[gidx] = Pw[lane * 66 + dd] + bias[oc] + xres[gidx];
        }
    }
}

// ---------------------------------------------------------------------------
// LayerNorm: 32 pixels x 512 channels per CTA, coalesced over l.
// ---------------------------------------------------------------------------
__global__ __launch_bounds__(256) void ln_kernel(
    const float* __restrict__ gamma, const float* __restrict__ beta,
    float* __restrict__ out)
{
    const int w = threadIdx.x >> 5, lane = threadIdx.x & 31;
    const int p0 = blockIdx.x * 32;
    const int b = p0 / LL;
    const int l = p0 % LL + lane;
    const float* yb = g_y + (size_t)b * CC * LL;

    float vals[64];
    float s = 0.f, s2 = 0.f;
    #pragma unroll
    for (int i = 0; i < 64; i++) {
        float v = yb[(size_t)(w * 64 + i) * LL + l];
        vals[i] = v; s += v; s2 += v * v;
    }
    __shared__ float ss[8][32], ss2[8][32];
    ss[w][lane] = s; ss2[w][lane] = s2;
    __syncthreads();
    float st = 0.f, st2 = 0.f;
    #pragma unroll
    for (int i = 0; i < 8; i++) { st += ss[i][lane]; st2 += ss2[i][lane]; }
    float mean = st * (1.f / CC);
    float var = st2 * (1.f / CC) - mean * mean;
    float rs = rsqrtf(var + 1e-5f);

    float* ob = out + (size_t)b * CC * LL;
    #pragma unroll
    for (int i = 0; i < 64; i++) {
        int c = w * 64 + i;
        ob[(size_t)c * LL + l] = (vals[i] - mean) * rs * gamma[c] + beta[c];
    }
}

// ---------------------------------------------------------------------------
extern "C" void kernel_launch(void* const* d_in, const int* in_sizes, int n_in,
                              void* d_out, int out_size)
{
    const float* x    = (const float*)d_in[0];
    const int*   mask = (const int*)d_in[1];
    const float* pos  = (const float*)d_in[2];
    const float* Wq = (const float*)d_in[3];
    const float* bq = (const float*)d_in[4];
    const float* Wk = (const float*)d_in[5];
    const float* bk = (const float*)d_in[6];
    const float* Wv = (const float*)d_in[7];
    const float* bv = (const float*)d_in[8];
    const float* Wo = (const float*)d_in[9];
    const float* bo = (const float*)d_in[10];
    const float* rel = (const float*)d_in[11];
    const float* gam = (const float*)d_in[12];
    const float* bet = (const float*)d_in[13];
    float* out = (float*)d_out;

    static bool attr_set = false;
    if (!attr_set) {
        cudaFuncSetAttribute(attn_kernel, cudaFuncAttributeMaxDynamicSharedMemorySize, A_BYTES);
        cudaFuncSetAttribute(gemm_qkv_mma, cudaFuncAttributeMaxDynamicSharedMemorySize, P_BYTES);
        cudaFuncSetAttribute(gemm_proj_mma, cudaFuncAttributeMaxDynamicSharedMemorySize, P_BYTES);
        attr_set = true;
    }

    add_pos_kernel<<<(BB * CC * LL) / 4 / 256, 256>>>(x, pos);
    gemm_qkv_mma<<<dim3(LL / 256, NH, BB * 3), 256, P_BYTES>>>(Wq, bq, Wk, bk, Wv, bv);
    pack_kernel<<<(NH * LL * MW) / 256, 256>>>(mask);
    attn_kernel<<<dim3(LL / 128, NH, BB), 128, A_BYTES>>>(rel);
    gemm_proj_mma<<<dim3(LL / 256, CC / 64, BB), 256, P_BYTES>>>(Wo, bo, x);
    ln_kernel<<<(BB * LL) / 32, 256>>>(gam, bet, out);
}